// round 15
// baseline (speedup 1.0000x reference)
#include <cuda_runtime.h>
#include <cuda_fp16.h>
#include <math.h>
#include <stdint.h>

#define HID   512
#define BATCH 64
#define NSEQ  128
#define TENC  256
#define TDEC  48
#define G3    1536   // 3*H
#define CIN   1024   // 2*H

#define SW_STRIDE 520   // persist: weight row stride (floats)
#define HCH 132         // persist: h chunk row stride (floats); 132%32=4 conflict-free

// ---------------- scratch ----------------
__device__ __align__(16) float g_GI0[(size_t)TENC * NSEQ * G3];
__device__ __align__(16) float g_GI1[(size_t)TDEC * NSEQ * G3];
__device__ __align__(16) __half g_Ah[(size_t)32768 * 1024];
__device__ __align__(16) __half g_A1h[(size_t)6144 * 512];
__device__ __align__(16) __half g_Bh[(size_t)1536 * 1024];
__device__ __align__(16) __half g_B1h[(size_t)1536 * 512];
__device__ float g_hA[NSEQ * HID];
__device__ float g_hB[NSEQ * HID];
// two-level barrier: g_bar[s*32] = sub-counter s (s=0..7), g_bar[8*32] = master
__device__ unsigned g_bar[9 * 32];

// ---------------- fp32x2 helpers (persist kernel) ----------------
__device__ __forceinline__ void fma2(unsigned long long& acc, double a, double b) {
    asm("fma.rn.f32x2 %0, %1, %2, %0;"
        : "+l"(acc)
        : "l"(__double_as_longlong(a)), "l"(__double_as_longlong(b)));
}
__device__ __forceinline__ float pairsum(unsigned long long v) {
    return __uint_as_float((unsigned)v) + __uint_as_float((unsigned)(v >> 32));
}
__device__ __forceinline__ float sigmoidf_(float x) { return 1.f / (1.f + expf(-x)); }

// ---------------- two-level monotonic grid barrier (round-14) ----------------
__device__ __forceinline__ void grid_barrier(unsigned ep, int sub) {
    __syncthreads();
    if (threadIdx.x == 0) {
        __threadfence();
        unsigned v = atomicAdd(&g_bar[sub * 32], 1u) + 1u;
        if ((v & 15u) == 0u) atomicAdd(&g_bar[8 * 32], 1u);
        const unsigned* p = &g_bar[8 * 32];
        unsigned tgt = 8u * ep;
        for (;;) {
            unsigned m;
            asm volatile("ld.relaxed.gpu.global.u32 %0, [%1];" : "=r"(m) : "l"(p) : "memory");
            if (m >= tgt) break;
        }
        __threadfence();
    }
    __syncthreads();
}

// ---------------- mma/ldmatrix/cp.async helpers (portable ISA) ----------------
__device__ __forceinline__ uint32_t smem_u32(const void* p) {
    uint32_t a;
    asm("{ .reg .u64 t; cvta.to.shared.u64 t, %1; cvt.u32.u64 %0, t; }" : "=r"(a) : "l"(p));
    return a;
}
__device__ __forceinline__ void ldsm4(uint32_t* r, uint32_t a) {
    asm volatile("ldmatrix.sync.aligned.m8n8.x4.shared.b16 {%0,%1,%2,%3}, [%4];"
                 : "=r"(r[0]), "=r"(r[1]), "=r"(r[2]), "=r"(r[3]) : "r"(a));
}
__device__ __forceinline__ void mma32(float* d, const uint32_t* a, uint32_t b0, uint32_t b1) {
    asm volatile("mma.sync.aligned.m16n8k16.row.col.f32.f16.f16.f32 "
                 "{%0,%1,%2,%3}, {%4,%5,%6,%7}, {%8,%9}, {%0,%1,%2,%3};"
                 : "+f"(d[0]), "+f"(d[1]), "+f"(d[2]), "+f"(d[3])
                 : "r"(a[0]), "r"(a[1]), "r"(a[2]), "r"(a[3]), "r"(b0), "r"(b1));
}
__device__ __forceinline__ void cpasync16(uint32_t s, const void* g) {
    asm volatile("cp.async.cg.shared.global [%0], [%1], 16;" :: "r"(s), "l"(g));
}
#define CP_COMMIT() asm volatile("cp.async.commit_group;")
#define CP_WAIT(n)  asm volatile("cp.async.wait_group %0;" :: "n"(n))

// ---------------- conversion kernels (fp16 hi plane only) ----------------
__global__ void conv_x0(const float* __restrict__ X0) {
    __shared__ float tile[32][33];
    int t0 = blockIdx.x * 32, c0 = blockIdx.y * 32, b = blockIdx.z;
    int x = threadIdx.x, y = threadIdx.y;
    #pragma unroll
    for (int yy = y; yy < 32; yy += 8)
        tile[yy][x] = X0[((size_t)(b * 1024 + c0 + yy)) * 512 + t0 + x];
    __syncthreads();
    #pragma unroll
    for (int yy = y; yy < 32; yy += 8) {
        size_t idx = (size_t)(b * 512 + t0 + yy) * 1024 + c0 + x;
        g_Ah[idx] = __float2half_rn(tile[x][yy]);
    }
}

__global__ void conv_x1(const float* __restrict__ X1) {
    __shared__ float tile[32][33];
    int t0 = blockIdx.x * 32, c0 = blockIdx.y * 32, b = blockIdx.z;
    int x = threadIdx.x, y = threadIdx.y;
    #pragma unroll
    for (int yy = y; yy < 32; yy += 8)
        tile[yy][x] = X1[((size_t)(b * 512 + c0 + yy)) * 96 + t0 + x];
    __syncthreads();
    #pragma unroll
    for (int yy = y; yy < 32; yy += 8) {
        size_t idx = (size_t)(b * 96 + t0 + yy) * 512 + c0 + x;
        g_A1h[idx] = __float2half_rn(tile[x][yy]);
    }
}

__global__ void conv_w(const float* __restrict__ src, __half* outh,
                       int Kout, int Kin, int koff, long total) {
    long i = (long)blockIdx.x * 256 + threadIdx.x;
    if (i >= total) return;
    long j = i / Kout, k = i - j * Kout;
    outh[i] = __float2half_rn(src[j * Kin + koff + k]);
}

__global__ void zero_h() {
    int i = blockIdx.x * 256 + threadIdx.x;
    if (i < NSEQ * HID) g_hA[i] = 0.f;
    if (i < 9 * 32) g_bar[i] = 0u;
}

// ---------------- single-pass fp16 GI GEMM (round-12, best measured) ----------------
#define TILE_B   10240
#define STAGE_B  (2 * TILE_B)
#define GEMM_SMEM (2 * STAGE_B)             // 40960

__global__ void __launch_bounds__(256, 2) gemm_mma(
    const __half* __restrict__ Ah, const __half* __restrict__ Bh,
    const float* __restrict__ bias, float* __restrict__ outGI, int K, int mode)
{
    extern __shared__ char smem[];
    const uint32_t sb = smem_u32(smem);
    const int tid  = threadIdx.x;
    const int wid  = tid >> 5;
    const int lane = tid & 31;
    const int j0 = blockIdx.x * 128;
    const int m0 = blockIdx.y * 128;
    const int warpM = (wid & 3) * 32;
    const int warpN = (wid >> 2) * 64;

    float acc[2][8][4];
    #pragma unroll
    for (int mt = 0; mt < 2; mt++)
        #pragma unroll
        for (int f = 0; f < 8; f++)
            #pragma unroll
            for (int r = 0; r < 4; r++) acc[mt][f][r] = 0.f;

    const int NC = K >> 5;

    auto load_chunk = [&](int ch, int stage) {
        uint32_t base = sb + stage * STAGE_B;
        int c0 = ch * 32;
        #pragma unroll
        for (int i = 0; i < 2; i++) {
            int idx = tid + 256 * i;
            int r = idx >> 2, s = idx & 3;
            uint32_t soff = (uint32_t)(r * 80 + s * 16);
            size_t ga = (size_t)(m0 + r) * K + c0 + s * 8;
            size_t gb = (size_t)(j0 + r) * K + c0 + s * 8;
            cpasync16(base + 0 * TILE_B + soff, Ah + ga);
            cpasync16(base + 1 * TILE_B + soff, Bh + gb);
        }
    };

    load_chunk(0, 0);
    CP_COMMIT();

    for (int ch = 0; ch < NC; ch++) {
        if (ch + 1 < NC) {
            load_chunk(ch + 1, (ch + 1) & 1);
            CP_COMMIT();
            CP_WAIT(1);
        } else {
            CP_WAIT(0);
        }
        __syncthreads();

        uint32_t base = sb + (ch & 1) * STAGE_B;
        #pragma unroll
        for (int k16 = 0; k16 < 2; k16++) {
            uint32_t koff = (uint32_t)(k16 * 32 + (lane >> 4) * 16);
            uint32_t ah[2][4];
            #pragma unroll
            for (int mt = 0; mt < 2; mt++) {
                uint32_t row = (uint32_t)(warpM + mt * 16 + (lane & 15));
                ldsm4(ah[mt], base + 0 * TILE_B + row * 80 + koff);
            }
            #pragma unroll
            for (int bt = 0; bt < 4; bt++) {
                uint32_t bh[4];
                uint32_t row = (uint32_t)(warpN + bt * 16 + (lane & 15));
                ldsm4(bh, base + 1 * TILE_B + row * 80 + koff);
                mma32(acc[0][bt * 2 + 0], ah[0], bh[0], bh[2]);
                mma32(acc[0][bt * 2 + 1], ah[0], bh[1], bh[3]);
                mma32(acc[1][bt * 2 + 0], ah[1], bh[0], bh[2]);
                mma32(acc[1][bt * 2 + 1], ah[1], bh[1], bh[3]);
            }
        }
        __syncthreads();
    }

    float2 bias2[8];
    #pragma unroll
    for (int bt = 0; bt < 4; bt++)
        #pragma unroll
        for (int hf = 0; hf < 2; hf++) {
            int j = j0 + warpN + bt * 16 + hf * 8 + (lane & 3) * 2;
            bias2[bt * 2 + hf] = make_float2(bias[j], bias[j + 1]);
        }

    size_t rb[4];
    #pragma unroll
    for (int mt = 0; mt < 2; mt++)
        #pragma unroll
        for (int u = 0; u < 2; u++) {
            int m = m0 + warpM + mt * 16 + u * 8 + (lane >> 2);
            int bb, t0;
            if (mode == 0) { t0 = m & 511; bb = m >> 9; }
            else           { bb = m / 96; t0 = m - bb * 96; }
            int n = ((t0 & 1) << 6) | bb;
            rb[mt * 2 + u] = ((size_t)((t0 >> 1) * NSEQ + n)) * G3;
        }

    #pragma unroll
    for (int mt = 0; mt < 2; mt++)
        #pragma unroll
        for (int bt = 0; bt < 4; bt++)
            #pragma unroll
            for (int hf = 0; hf < 2; hf++) {
                const float* ac = acc[mt][bt * 2 + hf];
                float2 bz = bias2[bt * 2 + hf];
                int jc = j0 + warpN + bt * 16 + hf * 8 + (lane & 3) * 2;
                float2 v0 = make_float2(ac[0] + bz.x, ac[1] + bz.y);
                float2 v1 = make_float2(ac[2] + bz.x, ac[3] + bz.y);
                *(float2*)(outGI + rb[mt * 2 + 0] + jc) = v0;
                *(float2*)(outGI + rb[mt * 2 + 1] + jc) = v1;
            }
}

// ---------------- persistent recurrence kernel ----------------
// Round-14 + 4x128k chunks staged via cp.async (4 syncs/step instead of 9).
__global__ void __launch_bounds__(256, 1) rnn_persist(
    const float* __restrict__ Whe, const float* __restrict__ bhe,
    const float* __restrict__ Whd, const float* __restrict__ Wid,
    const float* __restrict__ bhd, float* __restrict__ out)
{
    extern __shared__ float sm[];
    float* sw  = sm;                                  // 24 * 520
    float* sd0 = sm + 24 * SW_STRIDE;                 // 128 * 132
    float* sd1 = sd0 + 128 * HCH;                     // 128 * 132
    const uint32_t sb0 = smem_u32(sd0);
    const uint32_t sb1 = smem_u32(sd1);

    int tid = threadIdx.x;
    int jb  = blockIdx.x;
    int sub = jb & 7;
    int a   = tid >> 2;
    int b   = tid & 3;
    int n0  = a, n1 = a + 64;
    int jh  = jb * 4 + b;

    // staging map: idx = tid + 256*l (l=0..15): row = idx>>5, seg = idx&31
    int st_row = tid >> 5;        // + 8*l
    int st_seg = tid & 31;

    #pragma unroll
    for (int l = 0; l < 24; l++) {
        int idx = tid + 256 * l;
        int q = idx >> 9, k = idx & 511;
        int j = jb * 4 + (q & 3) + (q >> 2) * 512;
        sw[q * SW_STRIDE + k] = Whe[(size_t)j * 512 + k];
    }
    float bias[3];
    #pragma unroll
    for (int g = 0; g < 3; g++) bias[g] = bhe[jh + 512 * g];
    __syncthreads();

    const float* wp0 = sw + b * SW_STRIDE;
    const float* wp1 = sw + (4 + b) * SW_STRIDE;
    const float* wp2 = sw + (8 + b) * SW_STRIDE;

    const float* hin  = g_hA;
    float*       hout = g_hB;

    float hprev0 = 0.f, hprev1 = 0.f;
    unsigned ep = 0;

    float gi0r, gi0z, gi0n, gi1r, gi1z, gi1n;
    {
        const float* gp = g_GI0;
        gi0r = __ldg(gp + (size_t)n0 * G3 + jh);
        gi0z = __ldg(gp + (size_t)n0 * G3 + jh + 512);
        gi0n = __ldg(gp + (size_t)n0 * G3 + jh + 1024);
        gi1r = __ldg(gp + (size_t)n1 * G3 + jh);
        gi1z = __ldg(gp + (size_t)n1 * G3 + jh + 512);
        gi1n = __ldg(gp + (size_t)n1 * G3 + jh + 1024);
    }

    // chunk stager: copies h rows [0..128) cols [c*128, c*128+128) into buffer
    auto stage = [&](const float* src, int c, uint32_t dstb) {
        int k0 = c * 128;
        #pragma unroll
        for (int l = 0; l < 16; l++) {
            int row = st_row + 8 * l;
            cpasync16(dstb + (uint32_t)(row * HCH + st_seg * 4) * 4,
                      src + (size_t)row * 512 + k0 + st_seg * 4);
        }
        CP_COMMIT();
    };

    for (int t = 0; t < TENC; t++) {
        unsigned long long acc[2][3] = {{0ull,0ull,0ull},{0ull,0ull,0ull}};

        stage(hin, 0, sb0);
        CP_WAIT(0);
        __syncthreads();

        #pragma unroll
        for (int c = 0; c < 4; c++) {
            const float* shc = (c & 1) ? sd1 : sd0;
            if (c < 3) stage(hin, c + 1, (c & 1) ? sb0 : sb1);
            int k0 = c * 128;
            const float* hr0 = shc + n0 * HCH;
            const float* hr1 = shc + n1 * HCH;
            #pragma unroll 4
            for (int kk = 0; kk < 32; kk++) {
                double2 h0 = *(const double2*)(hr0 + kk * 4);
                double2 h1 = *(const double2*)(hr1 + kk * 4);
                double2 w0 = *(const double2*)(wp0 + k0 + kk * 4);
                double2 w1 = *(const double2*)(wp1 + k0 + kk * 4);
                double2 w2 = *(const double2*)(wp2 + k0 + kk * 4);
                fma2(acc[0][0], h0.x, w0.x); fma2(acc[0][0], h0.y, w0.y);
                fma2(acc[1][0], h1.x, w0.x); fma2(acc[1][0], h1.y, w0.y);
                fma2(acc[0][1], h0.x, w1.x); fma2(acc[0][1], h0.y, w1.y);
                fma2(acc[1][1], h1.x, w1.x); fma2(acc[1][1], h1.y, w1.y);
                fma2(acc[0][2], h0.x, w2.x); fma2(acc[0][2], h0.y, w2.y);
                fma2(acc[1][2], h1.x, w2.x); fma2(acc[1][2], h1.y, w2.y);
            }
            if (c < 3) {
                CP_WAIT(0);
                __syncthreads();
            }
        }

        {
            float ar = pairsum(acc[0][0]) + bias[0];
            float az = pairsum(acc[0][1]) + bias[1];
            float an = pairsum(acc[0][2]) + bias[2];
            float r = sigmoidf_(gi0r + ar);
            float z = sigmoidf_(gi0z + az);
            float nn = tanhf(gi0n + r * an);
            hprev0 = (1.f - z) * nn + z * hprev0;
            hout[n0 * 512 + jh] = hprev0;
        }
        {
            float ar = pairsum(acc[1][0]) + bias[0];
            float az = pairsum(acc[1][1]) + bias[1];
            float an = pairsum(acc[1][2]) + bias[2];
            float r = sigmoidf_(gi1r + ar);
            float z = sigmoidf_(gi1z + az);
            float nn = tanhf(gi1n + r * an);
            hprev1 = (1.f - z) * nn + z * hprev1;
            hout[n1 * 512 + jh] = hprev1;
        }

        const float* gp = (t + 1 < TENC) ? (g_GI0 + (size_t)(t + 1) * NSEQ * G3)
                                         : g_GI1;
        gi0r = __ldg(gp + (size_t)n0 * G3 + jh);
        gi0z = __ldg(gp + (size_t)n0 * G3 + jh + 512);
        gi0n = __ldg(gp + (size_t)n0 * G3 + jh + 1024);
        gi1r = __ldg(gp + (size_t)n1 * G3 + jh);
        gi1z = __ldg(gp + (size_t)n1 * G3 + jh + 512);
        gi1n = __ldg(gp + (size_t)n1 * G3 + jh + 1024);

        grid_barrier(++ep, sub);
        const float* tmp = hin; hin = hout; hout = (float*)tmp;
    }

    #pragma unroll
    for (int l = 0; l < 48; l++) {
        int idx = tid + 256 * l;
        int q2 = idx >> 9, k = idx & 511;
        if (q2 < 12) {
            int j = jb * 4 + (q2 & 3) + (q2 >> 2) * 512;
            sw[q2 * SW_STRIDE + k] = Whd[(size_t)j * 512 + k];
        } else {
            int q = q2 - 12;
            int j = jb * 4 + (q & 3) + (q >> 2) * 512;
            sw[q2 * SW_STRIDE + k] = Wid[(size_t)j * CIN + k];
        }
    }
    #pragma unroll
    for (int g = 0; g < 3; g++) bias[g] = bhd[jh + 512 * g];
    __syncthreads();

    const float* ip0 = sw + (12 + b) * SW_STRIDE;
    const float* ip1 = sw + (16 + b) * SW_STRIDE;
    const float* ip2 = sw + (20 + b) * SW_STRIDE;

    for (int t = 0; t < TDEC; t++) {
        unsigned long long accH[2][3] = {{0ull,0ull,0ull},{0ull,0ull,0ull}};
        unsigned long long accI[2][3] = {{0ull,0ull,0ull},{0ull,0ull,0ull}};

        stage(hin, 0, sb0);
        CP_WAIT(0);
        __syncthreads();

        #pragma unroll
        for (int c = 0; c < 4; c++) {
            const float* shc = (c & 1) ? sd1 : sd0;
            if (c < 3) stage(hin, c + 1, (c & 1) ? sb0 : sb1);
            int k0 = c * 128;
            const float* hr0 = shc + n0 * HCH;
            const float* hr1 = shc + n1 * HCH;
            #pragma unroll 2
            for (int kk = 0; kk < 32; kk++) {
                double2 h0 = *(const double2*)(hr0 + kk * 4);
                double2 h1 = *(const double2*)(hr1 + kk * 4);
                double2 w0 = *(const double2*)(wp0 + k0 + kk * 4);
                double2 w1 = *(const double2*)(wp1 + k0 + kk * 4);
                double2 w2 = *(const double2*)(wp2 + k0 + kk * 4);
                fma2(accH[0][0], h0.x, w0.x); fma2(accH[0][0], h0.y, w0.y);
                fma2(accH[1][0], h1.x, w0.x); fma2(accH[1][0], h1.y, w0.y);
                fma2(accH[0][1], h0.x, w1.x); fma2(accH[0][1], h0.y, w1.y);
                fma2(accH[1][1], h1.x, w1.x); fma2(accH[1][1], h1.y, w1.y);
                fma2(accH[0][2], h0.x, w2.x); fma2(accH[0][2], h0.y, w2.y);
                fma2(accH[1][2], h1.x, w2.x); fma2(accH[1][2], h1.y, w2.y);
                double2 v0 = *(const double2*)(ip0 + k0 + kk * 4);
                double2 v1 = *(const double2*)(ip1 + k0 + kk * 4);
                double2 v2 = *(const double2*)(ip2 + k0 + kk * 4);
                fma2(accI[0][0], h0.x, v0.x); fma2(accI[0][0], h0.y, v0.y);
                fma2(accI[1][0], h1.x, v0.x); fma2(accI[1][0], h1.y, v0.y);
                fma2(accI[0][1], h0.x, v1.x); fma2(accI[0][1], h0.y, v1.y);
                fma2(accI[1][1], h1.x, v1.x); fma2(accI[1][1], h1.y, v1.y);
                fma2(accI[0][2], h0.x, v2.x); fma2(accI[0][2], h0.y, v2.y);
                fma2(accI[1][2], h1.x, v2.x); fma2(accI[1][2], h1.y, v2.y);
            }
            if (c < 3) {
                CP_WAIT(0);
                __syncthreads();
            }
        }

        {
            float hr = pairsum(accH[0][0]) + bias[0];
            float hz = pairsum(accH[0][1]) + bias[1];
            float hn = pairsum(accH[0][2]) + bias[2];
            float r = sigmoidf_(gi0r + pairsum(accI[0][0]) + hr);
            float z = sigmoidf_(gi0z + pairsum(accI[0][1]) + hz);
            float nn = tanhf(gi0n + pairsum(accI[0][2]) + r * hn);
            hprev0 = (1.f - z) * nn + z * hprev0;
            hout[n0 * 512 + jh] = hprev0;
            out[((size_t)a * HID + jh) * 96 + 2 * t] = hprev0;
        }
        {
            float hr = pairsum(accH[1][0]) + bias[0];
            float hz = pairsum(accH[1][1]) + bias[1];
            float hn = pairsum(accH[1][2]) + bias[2];
            float r = sigmoidf_(gi1r + pairsum(accI[1][0]) + hr);
            float z = sigmoidf_(gi1z + pairsum(accI[1][1]) + hz);
            float nn = tanhf(gi1n + pairsum(accI[1][2]) + r * hn);
            hprev1 = (1.f - z) * nn + z * hprev1;
            hout[n1 * 512 + jh] = hprev1;
            out[((size_t)a * HID + jh) * 96 + 2 * t + 1] = hprev1;
        }

        if (t < TDEC - 1) {
            const float* gp = g_GI1 + (size_t)(t + 1) * NSEQ * G3;
            gi0r = __ldg(gp + (size_t)n0 * G3 + jh);
            gi0z = __ldg(gp + (size_t)n0 * G3 + jh + 512);
            gi0n = __ldg(gp + (size_t)n0 * G3 + jh + 1024);
            gi1r = __ldg(gp + (size_t)n1 * G3 + jh);
            gi1z = __ldg(gp + (size_t)n1 * G3 + jh + 512);
            gi1n = __ldg(gp + (size_t)n1 * G3 + jh + 1024);
            grid_barrier(++ep, sub);
            const float* tmp = hin; hin = hout; hout = (float*)tmp;
        }
    }
}

// ---------------- launch ----------------
extern "C" void kernel_launch(void* const* d_in, const int* in_sizes, int n_in,
                              void* d_out, int out_size) {
    const float* X0  = (const float*)d_in[0];
    const float* X1  = (const float*)d_in[1];
    const float* Wie = (const float*)d_in[3];
    const float* Whe = (const float*)d_in[4];
    const float* bie = (const float*)d_in[5];
    const float* bhe = (const float*)d_in[6];
    const float* Wid = (const float*)d_in[7];
    const float* Whd = (const float*)d_in[8];
    const float* bid = (const float*)d_in[9];
    const float* bhd = (const float*)d_in[10];
    float* out = (float*)d_out;

    const int SMEM_P = (24 * SW_STRIDE + 2 * 128 * HCH) * 4;   // 185,088 B
    cudaFuncSetAttribute(rnn_persist, cudaFuncAttributeMaxDynamicSharedMemorySize, SMEM_P);
    cudaFuncSetAttribute(gemm_mma, cudaFuncAttributeMaxDynamicSharedMemorySize, GEMM_SMEM);

    __half *Ah, *A1h, *Bh, *B1h;
    cudaGetSymbolAddress((void**)&Ah,  g_Ah);
    cudaGetSymbolAddress((void**)&A1h, g_A1h);
    cudaGetSymbolAddress((void**)&Bh,  g_Bh);
    cudaGetSymbolAddress((void**)&B1h, g_B1h);
    float *GI0, *GI1;
    cudaGetSymbolAddress((void**)&GI0, g_GI0);
    cudaGetSymbolAddress((void**)&GI1, g_GI1);

    dim3 tb(32, 8);
    conv_x0<<<dim3(16, 32, 64), tb>>>(X0);
    conv_x1<<<dim3(3, 16, 64), tb>>>(X1);
    conv_w<<<(1536 * 1024 + 255) / 256, 256>>>(Wie, Bh, 1024, 1024, 0, (long)1536 * 1024);
    conv_w<<<(1536 * 512 + 255) / 256, 256>>>(Wid, B1h, 512, 1024, 512, (long)1536 * 512);
    zero_h<<<256, 256>>>();

    gemm_mma<<<dim3(12, 256), 256, GEMM_SMEM>>>(Ah, Bh, bie, GI0, 1024, 0);
    gemm_mma<<<dim3(12, 48), 256, GEMM_SMEM>>>(A1h, B1h, bid, GI1, 512, 1);

    rnn_persist<<<128, 256, SMEM_P>>>(Whe, bhe, Whd, Wid, bhd, out);
}

// round 16
// speedup vs baseline: 1.0371x; 1.0371x over previous
#include <cuda_runtime.h>
#include <cuda_fp16.h>
#include <math.h>
#include <stdint.h>

#define HID   512
#define BATCH 64
#define NSEQ  128
#define TENC  256
#define TDEC  48
#define G3    1536   // 3*H
#define CIN   1024   // 2*H

#define SW_STRIDE 520   // persist: weight row stride
#define SH_STRIDE 68    // persist: h row stride

// ---------------- scratch ----------------
__device__ __align__(16) float g_GI0[(size_t)TENC * NSEQ * G3];
__device__ __align__(16) float g_GI1[(size_t)TDEC * NSEQ * G3];
__device__ __align__(16) __half g_Ah[(size_t)32768 * 1024];
__device__ __align__(16) __half g_A1h[(size_t)6144 * 512];
__device__ __align__(16) __half g_Bh[(size_t)1536 * 1024];
__device__ __align__(16) __half g_B1h[(size_t)1536 * 512];
__device__ __align__(16) __half g_hA[NSEQ * HID];   // fp16 broadcast copy of h
__device__ __align__(16) __half g_hB[NSEQ * HID];
// two-level barrier: g_bar[s*32] = sub-counter s (s=0..7), g_bar[8*32] = master
__device__ unsigned g_bar[9 * 32];

// ---------------- fp32x2 helpers (persist kernel) ----------------
__device__ __forceinline__ void fma2(unsigned long long& acc, double a, double b) {
    asm("fma.rn.f32x2 %0, %1, %2, %0;"
        : "+l"(acc)
        : "l"(__double_as_longlong(a)), "l"(__double_as_longlong(b)));
}
__device__ __forceinline__ float pairsum(unsigned long long v) {
    return __uint_as_float((unsigned)v) + __uint_as_float((unsigned)(v >> 32));
}
__device__ __forceinline__ float sigmoidf_(float x) { return 1.f / (1.f + expf(-x)); }

// ---------------- two-level monotonic grid barrier (round-14) ----------------
__device__ __forceinline__ void grid_barrier(unsigned ep, int sub) {
    __syncthreads();
    if (threadIdx.x == 0) {
        __threadfence();
        unsigned v = atomicAdd(&g_bar[sub * 32], 1u) + 1u;
        if ((v & 15u) == 0u) atomicAdd(&g_bar[8 * 32], 1u);
        const unsigned* p = &g_bar[8 * 32];
        unsigned tgt = 8u * ep;
        for (;;) {
            unsigned m;
            asm volatile("ld.relaxed.gpu.global.u32 %0, [%1];" : "=r"(m) : "l"(p) : "memory");
            if (m >= tgt) break;
        }
        __threadfence();
    }
    __syncthreads();
}

// ---------------- mma/ldmatrix/cp.async helpers (portable ISA) ----------------
__device__ __forceinline__ uint32_t smem_u32(const void* p) {
    uint32_t a;
    asm("{ .reg .u64 t; cvta.to.shared.u64 t, %1; cvt.u32.u64 %0, t; }" : "=r"(a) : "l"(p));
    return a;
}
__device__ __forceinline__ void ldsm4(uint32_t* r, uint32_t a) {
    asm volatile("ldmatrix.sync.aligned.m8n8.x4.shared.b16 {%0,%1,%2,%3}, [%4];"
                 : "=r"(r[0]), "=r"(r[1]), "=r"(r[2]), "=r"(r[3]) : "r"(a));
}
__device__ __forceinline__ void mma32(float* d, const uint32_t* a, uint32_t b0, uint32_t b1) {
    asm volatile("mma.sync.aligned.m16n8k16.row.col.f32.f16.f16.f32 "
                 "{%0,%1,%2,%3}, {%4,%5,%6,%7}, {%8,%9}, {%0,%1,%2,%3};"
                 : "+f"(d[0]), "+f"(d[1]), "+f"(d[2]), "+f"(d[3])
                 : "r"(a[0]), "r"(a[1]), "r"(a[2]), "r"(a[3]), "r"(b0), "r"(b1));
}
__device__ __forceinline__ void cpasync16(uint32_t s, const void* g) {
    asm volatile("cp.async.cg.shared.global [%0], [%1], 16;" :: "r"(s), "l"(g));
}
#define CP_COMMIT() asm volatile("cp.async.commit_group;")
#define CP_WAIT(n)  asm volatile("cp.async.wait_group %0;" :: "n"(n))

// ---------------- conversion kernels (fp16 hi plane only) ----------------
__global__ void conv_x0(const float* __restrict__ X0) {
    __shared__ float tile[32][33];
    int t0 = blockIdx.x * 32, c0 = blockIdx.y * 32, b = blockIdx.z;
    int x = threadIdx.x, y = threadIdx.y;
    #pragma unroll
    for (int yy = y; yy < 32; yy += 8)
        tile[yy][x] = X0[((size_t)(b * 1024 + c0 + yy)) * 512 + t0 + x];
    __syncthreads();
    #pragma unroll
    for (int yy = y; yy < 32; yy += 8) {
        size_t idx = (size_t)(b * 512 + t0 + yy) * 1024 + c0 + x;
        g_Ah[idx] = __float2half_rn(tile[x][yy]);
    }
}

__global__ void conv_x1(const float* __restrict__ X1) {
    __shared__ float tile[32][33];
    int t0 = blockIdx.x * 32, c0 = blockIdx.y * 32, b = blockIdx.z;
    int x = threadIdx.x, y = threadIdx.y;
    #pragma unroll
    for (int yy = y; yy < 32; yy += 8)
        tile[yy][x] = X1[((size_t)(b * 512 + c0 + yy)) * 96 + t0 + x];
    __syncthreads();
    #pragma unroll
    for (int yy = y; yy < 32; yy += 8) {
        size_t idx = (size_t)(b * 96 + t0 + yy) * 512 + c0 + x;
        g_A1h[idx] = __float2half_rn(tile[x][yy]);
    }
}

__global__ void conv_w(const float* __restrict__ src, __half* outh,
                       int Kout, int Kin, int koff, long total) {
    long i = (long)blockIdx.x * 256 + threadIdx.x;
    if (i >= total) return;
    long j = i / Kout, k = i - j * Kout;
    outh[i] = __float2half_rn(src[j * Kin + koff + k]);
}

__global__ void zero_h() {
    int i = blockIdx.x * 256 + threadIdx.x;
    if (i < NSEQ * HID) g_hA[i] = __float2half_rn(0.f);
    if (i < 9 * 32) g_bar[i] = 0u;
}

// ---------------- single-pass fp16 GI GEMM (round-12, best measured) ----------------
#define TILE_B   10240
#define STAGE_B  (2 * TILE_B)
#define GEMM_SMEM (2 * STAGE_B)             // 40960

__global__ void __launch_bounds__(256, 2) gemm_mma(
    const __half* __restrict__ Ah, const __half* __restrict__ Bh,
    const float* __restrict__ bias, float* __restrict__ outGI, int K, int mode)
{
    extern __shared__ char smem[];
    const uint32_t sb = smem_u32(smem);
    const int tid  = threadIdx.x;
    const int wid  = tid >> 5;
    const int lane = tid & 31;
    const int j0 = blockIdx.x * 128;
    const int m0 = blockIdx.y * 128;
    const int warpM = (wid & 3) * 32;
    const int warpN = (wid >> 2) * 64;

    float acc[2][8][4];
    #pragma unroll
    for (int mt = 0; mt < 2; mt++)
        #pragma unroll
        for (int f = 0; f < 8; f++)
            #pragma unroll
            for (int r = 0; r < 4; r++) acc[mt][f][r] = 0.f;

    const int NC = K >> 5;

    auto load_chunk = [&](int ch, int stage) {
        uint32_t base = sb + stage * STAGE_B;
        int c0 = ch * 32;
        #pragma unroll
        for (int i = 0; i < 2; i++) {
            int idx = tid + 256 * i;
            int r = idx >> 2, s = idx & 3;
            uint32_t soff = (uint32_t)(r * 80 + s * 16);
            size_t ga = (size_t)(m0 + r) * K + c0 + s * 8;
            size_t gb = (size_t)(j0 + r) * K + c0 + s * 8;
            cpasync16(base + 0 * TILE_B + soff, Ah + ga);
            cpasync16(base + 1 * TILE_B + soff, Bh + gb);
        }
    };

    load_chunk(0, 0);
    CP_COMMIT();

    for (int ch = 0; ch < NC; ch++) {
        if (ch + 1 < NC) {
            load_chunk(ch + 1, (ch + 1) & 1);
            CP_COMMIT();
            CP_WAIT(1);
        } else {
            CP_WAIT(0);
        }
        __syncthreads();

        uint32_t base = sb + (ch & 1) * STAGE_B;
        #pragma unroll
        for (int k16 = 0; k16 < 2; k16++) {
            uint32_t koff = (uint32_t)(k16 * 32 + (lane >> 4) * 16);
            uint32_t ah[2][4];
            #pragma unroll
            for (int mt = 0; mt < 2; mt++) {
                uint32_t row = (uint32_t)(warpM + mt * 16 + (lane & 15));
                ldsm4(ah[mt], base + 0 * TILE_B + row * 80 + koff);
            }
            #pragma unroll
            for (int bt = 0; bt < 4; bt++) {
                uint32_t bh[4];
                uint32_t row = (uint32_t)(warpN + bt * 16 + (lane & 15));
                ldsm4(bh, base + 1 * TILE_B + row * 80 + koff);
                mma32(acc[0][bt * 2 + 0], ah[0], bh[0], bh[2]);
                mma32(acc[0][bt * 2 + 1], ah[0], bh[1], bh[3]);
                mma32(acc[1][bt * 2 + 0], ah[1], bh[0], bh[2]);
                mma32(acc[1][bt * 2 + 1], ah[1], bh[1], bh[3]);
            }
        }
        __syncthreads();
    }

    float2 bias2[8];
    #pragma unroll
    for (int bt = 0; bt < 4; bt++)
        #pragma unroll
        for (int hf = 0; hf < 2; hf++) {
            int j = j0 + warpN + bt * 16 + hf * 8 + (lane & 3) * 2;
            bias2[bt * 2 + hf] = make_float2(bias[j], bias[j + 1]);
        }

    size_t rb[4];
    #pragma unroll
    for (int mt = 0; mt < 2; mt++)
        #pragma unroll
        for (int u = 0; u < 2; u++) {
            int m = m0 + warpM + mt * 16 + u * 8 + (lane >> 2);
            int bb, t0;
            if (mode == 0) { t0 = m & 511; bb = m >> 9; }
            else           { bb = m / 96; t0 = m - bb * 96; }
            int n = ((t0 & 1) << 6) | bb;
            rb[mt * 2 + u] = ((size_t)((t0 >> 1) * NSEQ + n)) * G3;
        }

    #pragma unroll
    for (int mt = 0; mt < 2; mt++)
        #pragma unroll
        for (int bt = 0; bt < 4; bt++)
            #pragma unroll
            for (int hf = 0; hf < 2; hf++) {
                const float* ac = acc[mt][bt * 2 + hf];
                float2 bz = bias2[bt * 2 + hf];
                int jc = j0 + warpN + bt * 16 + hf * 8 + (lane & 3) * 2;
                float2 v0 = make_float2(ac[0] + bz.x, ac[1] + bz.y);
                float2 v1 = make_float2(ac[2] + bz.x, ac[3] + bz.y);
                *(float2*)(outGI + rb[mt * 2 + 0] + jc) = v0;
                *(float2*)(outGI + rb[mt * 2 + 1] + jc) = v1;
            }
}

// ---------------- persistent recurrence kernel ----------------
// Round-14 structure; h broadcast stored fp16 (halves L2 + staging traffic).
// Gate math and SMEM layout stay fp32; own-state hprev carried exactly in regs.
__global__ void __launch_bounds__(256, 1) rnn_persist(
    const float* __restrict__ Whe, const float* __restrict__ bhe,
    const float* __restrict__ Whd, const float* __restrict__ Wid,
    const float* __restrict__ bhd, float* __restrict__ out)
{
    extern __shared__ float sm[];
    float* sw  = sm;                                  // 24 * 520
    float* sh0 = sm + 24 * SW_STRIDE;                 // 128 * 68
    float* sh1 = sh0 + 128 * SH_STRIDE;               // 128 * 68

    int tid = threadIdx.x;
    int jb  = blockIdx.x;
    int sub = jb & 7;
    int a   = tid >> 2;
    int b   = tid & 3;
    int n0  = a, n1 = a + 64;
    int jh  = jb * 4 + b;

    // staging map: idx4 = tid + 256*l (l=0..3): row = idx4>>3 (0..127), seg = idx4&7
    int st_row = tid >> 3;       // rows covered with l via +32
    int st_seg = tid & 7;

    #pragma unroll
    for (int l = 0; l < 24; l++) {
        int idx = tid + 256 * l;
        int q = idx >> 9, k = idx & 511;
        int j = jb * 4 + (q & 3) + (q >> 2) * 512;
        sw[q * SW_STRIDE + k] = Whe[(size_t)j * 512 + k];
    }
    float bias[3];
    #pragma unroll
    for (int g = 0; g < 3; g++) bias[g] = bhe[jh + 512 * g];
    __syncthreads();

    const float* wp0 = sw + b * SW_STRIDE;
    const float* wp1 = sw + (4 + b) * SW_STRIDE;
    const float* wp2 = sw + (8 + b) * SW_STRIDE;

    const __half* hin  = g_hA;
    __half*       hout = g_hB;

    float hprev0 = 0.f, hprev1 = 0.f;
    unsigned ep = 0;

    float gi0r, gi0z, gi0n, gi1r, gi1z, gi1n;
    {
        const float* gp = g_GI0;
        gi0r = __ldg(gp + (size_t)n0 * G3 + jh);
        gi0z = __ldg(gp + (size_t)n0 * G3 + jh + 512);
        gi0n = __ldg(gp + (size_t)n0 * G3 + jh + 1024);
        gi1r = __ldg(gp + (size_t)n1 * G3 + jh);
        gi1z = __ldg(gp + (size_t)n1 * G3 + jh + 512);
        gi1n = __ldg(gp + (size_t)n1 * G3 + jh + 1024);
    }

    // fp16 chunk load (8 halves) -> fp32 SMEM store helper
    auto sts_conv = [&](float* dst, uint4 v) {
        __half2* hp = (__half2*)&v;
        float2 p0 = __half22float2(hp[0]);
        float2 p1 = __half22float2(hp[1]);
        float2 p2 = __half22float2(hp[2]);
        float2 p3 = __half22float2(hp[3]);
        float4 f0 = make_float4(p0.x, p0.y, p1.x, p1.y);
        float4 f1 = make_float4(p2.x, p2.y, p3.x, p3.y);
        *(float4*)(dst)     = f0;
        *(float4*)(dst + 4) = f1;
    };

    for (int t = 0; t < TENC; t++) {
        unsigned long long acc[2][3] = {{0ull,0ull,0ull},{0ull,0ull,0ull}};

        // prologue: stage chunk 0 (128 rows x 64 k), 4 x uint4 (8 halves) per thread
        uint4 preg[4];
        #pragma unroll
        for (int l = 0; l < 4; l++)
            preg[l] = *(const uint4*)(hin + (size_t)(st_row + 32 * l) * 512 + st_seg * 8);
        #pragma unroll
        for (int l = 0; l < 4; l++)
            sts_conv(sh0 + (st_row + 32 * l) * SH_STRIDE + st_seg * 8, preg[l]);
        __syncthreads();

        #pragma unroll
        for (int c = 0; c < 8; c++) {
            const float* shc = (c & 1) ? sh1 : sh0;
            float*       shn = (c & 1) ? sh0 : sh1;
            int k0 = c * 64;
            if (c < 7) {
                #pragma unroll
                for (int l = 0; l < 4; l++)
                    preg[l] = *(const uint4*)(hin + (size_t)(st_row + 32 * l) * 512 +
                                              (k0 + 64) + st_seg * 8);
            }
            #pragma unroll
            for (int kk = 0; kk < 16; kk++) {
                double2 h0 = *(const double2*)(shc + n0 * SH_STRIDE + kk * 4);
                double2 h1 = *(const double2*)(shc + n1 * SH_STRIDE + kk * 4);
                double2 w0 = *(const double2*)(wp0 + k0 + kk * 4);
                double2 w1 = *(const double2*)(wp1 + k0 + kk * 4);
                double2 w2 = *(const double2*)(wp2 + k0 + kk * 4);
                fma2(acc[0][0], h0.x, w0.x); fma2(acc[0][0], h0.y, w0.y);
                fma2(acc[1][0], h1.x, w0.x); fma2(acc[1][0], h1.y, w0.y);
                fma2(acc[0][1], h0.x, w1.x); fma2(acc[0][1], h0.y, w1.y);
                fma2(acc[1][1], h1.x, w1.x); fma2(acc[1][1], h1.y, w1.y);
                fma2(acc[0][2], h0.x, w2.x); fma2(acc[0][2], h0.y, w2.y);
                fma2(acc[1][2], h1.x, w2.x); fma2(acc[1][2], h1.y, w2.y);
            }
            if (c < 7) {
                #pragma unroll
                for (int l = 0; l < 4; l++)
                    sts_conv(shn + (st_row + 32 * l) * SH_STRIDE + st_seg * 8, preg[l]);
            }
            __syncthreads();
        }

        {
            float ar = pairsum(acc[0][0]) + bias[0];
            float az = pairsum(acc[0][1]) + bias[1];
            float an = pairsum(acc[0][2]) + bias[2];
            float r = sigmoidf_(gi0r + ar);
            float z = sigmoidf_(gi0z + az);
            float nn = tanhf(gi0n + r * an);
            hprev0 = (1.f - z) * nn + z * hprev0;
            hout[n0 * 512 + jh] = __float2half_rn(hprev0);
        }
        {
            float ar = pairsum(acc[1][0]) + bias[0];
            float az = pairsum(acc[1][1]) + bias[1];
            float an = pairsum(acc[1][2]) + bias[2];
            float r = sigmoidf_(gi1r + ar);
            float z = sigmoidf_(gi1z + az);
            float nn = tanhf(gi1n + r * an);
            hprev1 = (1.f - z) * nn + z * hprev1;
            hout[n1 * 512 + jh] = __float2half_rn(hprev1);
        }

        const float* gp = (t + 1 < TENC) ? (g_GI0 + (size_t)(t + 1) * NSEQ * G3)
                                         : g_GI1;
        gi0r = __ldg(gp + (size_t)n0 * G3 + jh);
        gi0z = __ldg(gp + (size_t)n0 * G3 + jh + 512);
        gi0n = __ldg(gp + (size_t)n0 * G3 + jh + 1024);
        gi1r = __ldg(gp + (size_t)n1 * G3 + jh);
        gi1z = __ldg(gp + (size_t)n1 * G3 + jh + 512);
        gi1n = __ldg(gp + (size_t)n1 * G3 + jh + 1024);

        grid_barrier(++ep, sub);
        const __half* tmp = hin; hin = hout; hout = (__half*)tmp;
    }

    #pragma unroll
    for (int l = 0; l < 48; l++) {
        int idx = tid + 256 * l;
        int q2 = idx >> 9, k = idx & 511;
        if (q2 < 12) {
            int j = jb * 4 + (q2 & 3) + (q2 >> 2) * 512;
            sw[q2 * SW_STRIDE + k] = Whd[(size_t)j * 512 + k];
        } else {
            int q = q2 - 12;
            int j = jb * 4 + (q & 3) + (q >> 2) * 512;
            sw[q2 * SW_STRIDE + k] = Wid[(size_t)j * CIN + k];
        }
    }
    #pragma unroll
    for (int g = 0; g < 3; g++) bias[g] = bhd[jh + 512 * g];
    __syncthreads();

    const float* ip0 = sw + (12 + b) * SW_STRIDE;
    const float* ip1 = sw + (16 + b) * SW_STRIDE;
    const float* ip2 = sw + (20 + b) * SW_STRIDE;

    for (int t = 0; t < TDEC; t++) {
        unsigned long long accH[2][3] = {{0ull,0ull,0ull},{0ull,0ull,0ull}};
        unsigned long long accI[2][3] = {{0ull,0ull,0ull},{0ull,0ull,0ull}};

        uint4 preg[4];
        #pragma unroll
        for (int l = 0; l < 4; l++)
            preg[l] = *(const uint4*)(hin + (size_t)(st_row + 32 * l) * 512 + st_seg * 8);
        #pragma unroll
        for (int l = 0; l < 4; l++)
            sts_conv(sh0 + (st_row + 32 * l) * SH_STRIDE + st_seg * 8, preg[l]);
        __syncthreads();

        #pragma unroll
        for (int c = 0; c < 8; c++) {
            const float* shc = (c & 1) ? sh1 : sh0;
            float*       shn = (c & 1) ? sh0 : sh1;
            int k0 = c * 64;
            if (c < 7) {
                #pragma unroll
                for (int l = 0; l < 4; l++)
                    preg[l] = *(const uint4*)(hin + (size_t)(st_row + 32 * l) * 512 +
                                              (k0 + 64) + st_seg * 8);
            }
            #pragma unroll
            for (int kk = 0; kk < 16; kk++) {
                double2 h0 = *(const double2*)(shc + n0 * SH_STRIDE + kk * 4);
                double2 h1 = *(const double2*)(shc + n1 * SH_STRIDE + kk * 4);
                double2 w0 = *(const double2*)(wp0 + k0 + kk * 4);
                double2 w1 = *(const double2*)(wp1 + k0 + kk * 4);
                double2 w2 = *(const double2*)(wp2 + k0 + kk * 4);
                fma2(accH[0][0], h0.x, w0.x); fma2(accH[0][0], h0.y, w0.y);
                fma2(accH[1][0], h1.x, w0.x); fma2(accH[1][0], h1.y, w0.y);
                fma2(accH[0][1], h0.x, w1.x); fma2(accH[0][1], h0.y, w1.y);
                fma2(accH[1][1], h1.x, w1.x); fma2(accH[1][1], h1.y, w1.y);
                fma2(accH[0][2], h0.x, w2.x); fma2(accH[0][2], h0.y, w2.y);
                fma2(accH[1][2], h1.x, w2.x); fma2(accH[1][2], h1.y, w2.y);
                double2 v0 = *(const double2*)(ip0 + k0 + kk * 4);
                double2 v1 = *(const double2*)(ip1 + k0 + kk * 4);
                double2 v2 = *(const double2*)(ip2 + k0 + kk * 4);
                fma2(accI[0][0], h0.x, v0.x); fma2(accI[0][0], h0.y, v0.y);
                fma2(accI[1][0], h1.x, v0.x); fma2(accI[1][0], h1.y, v0.y);
                fma2(accI[0][1], h0.x, v1.x); fma2(accI[0][1], h0.y, v1.y);
                fma2(accI[1][1], h1.x, v1.x); fma2(accI[1][1], h1.y, v1.y);
                fma2(accI[0][2], h0.x, v2.x); fma2(accI[0][2], h0.y, v2.y);
                fma2(accI[1][2], h1.x, v2.x); fma2(accI[1][2], h1.y, v2.y);
            }
            if (c < 7) {
                #pragma unroll
                for (int l = 0; l < 4; l++)
                    sts_conv(shn + (st_row + 32 * l) * SH_STRIDE + st_seg * 8, preg[l]);
            }
            __syncthreads();
        }

        {
            float hr = pairsum(accH[0][0]) + bias[0];
            float hz = pairsum(accH[0][1]) + bias[1];
            float hn = pairsum(accH[0][2]) + bias[2];
            float r = sigmoidf_(gi0r + pairsum(accI[0][0]) + hr);
            float z = sigmoidf_(gi0z + pairsum(accI[0][1]) + hz);
            float nn = tanhf(gi0n + pairsum(accI[0][2]) + r * hn);
            hprev0 = (1.f - z) * nn + z * hprev0;
            hout[n0 * 512 + jh] = __float2half_rn(hprev0);
            out[((size_t)a * HID + jh) * 96 + 2 * t] = hprev0;
        }
        {
            float hr = pairsum(accH[1][0]) + bias[0];
            float hz = pairsum(accH[1][1]) + bias[1];
            float hn = pairsum(accH[1][2]) + bias[2];
            float r = sigmoidf_(gi1r + pairsum(accI[1][0]) + hr);
            float z = sigmoidf_(gi1z + pairsum(accI[1][1]) + hz);
            float nn = tanhf(gi1n + pairsum(accI[1][2]) + r * hn);
            hprev1 = (1.f - z) * nn + z * hprev1;
            hout[n1 * 512 + jh] = __float2half_rn(hprev1);
            out[((size_t)a * HID + jh) * 96 + 2 * t + 1] = hprev1;
        }

        if (t < TDEC - 1) {
            const float* gp = g_GI1 + (size_t)(t + 1) * NSEQ * G3;
            gi0r = __ldg(gp + (size_t)n0 * G3 + jh);
            gi0z = __ldg(gp + (size_t)n0 * G3 + jh + 512);
            gi0n = __ldg(gp + (size_t)n0 * G3 + jh + 1024);
            gi1r = __ldg(gp + (size_t)n1 * G3 + jh);
            gi1z = __ldg(gp + (size_t)n1 * G3 + jh + 512);
            gi1n = __ldg(gp + (size_t)n1 * G3 + jh + 1024);
            grid_barrier(++ep, sub);
            const __half* tmp = hin; hin = hout; hout = (__half*)tmp;
        }
    }
}

// ---------------- launch (serial, round-12/14 structure) ----------------
extern "C" void kernel_launch(void* const* d_in, const int* in_sizes, int n_in,
                              void* d_out, int out_size) {
    const float* X0  = (const float*)d_in[0];
    const float* X1  = (const float*)d_in[1];
    const float* Wie = (const float*)d_in[3];
    const float* Whe = (const float*)d_in[4];
    const float* bie = (const float*)d_in[5];
    const float* bhe = (const float*)d_in[6];
    const float* Wid = (const float*)d_in[7];
    const float* Whd = (const float*)d_in[8];
    const float* bid = (const float*)d_in[9];
    const float* bhd = (const float*)d_in[10];
    float* out = (float*)d_out;

    const int SMEM_P = (24 * SW_STRIDE + 2 * 128 * SH_STRIDE) * 4;  // 119552 B
    cudaFuncSetAttribute(rnn_persist, cudaFuncAttributeMaxDynamicSharedMemorySize, SMEM_P);
    cudaFuncSetAttribute(gemm_mma, cudaFuncAttributeMaxDynamicSharedMemorySize, GEMM_SMEM);

    __half *Ah, *A1h, *Bh, *B1h;
    cudaGetSymbolAddress((void**)&Ah,  g_Ah);
    cudaGetSymbolAddress((void**)&A1h, g_A1h);
    cudaGetSymbolAddress((void**)&Bh,  g_Bh);
    cudaGetSymbolAddress((void**)&B1h, g_B1h);
    float *GI0, *GI1;
    cudaGetSymbolAddress((void**)&GI0, g_GI0);
    cudaGetSymbolAddress((void**)&GI1, g_GI1);

    dim3 tb(32, 8);
    conv_x0<<<dim3(16, 32, 64), tb>>>(X0);
    conv_x1<<<dim3(3, 16, 64), tb>>>(X1);
    conv_w<<<(1536 * 1024 + 255) / 256, 256>>>(Wie, Bh, 1024, 1024, 0, (long)1536 * 1024);
    conv_w<<<(1536 * 512 + 255) / 256, 256>>>(Wid, B1h, 512, 1024, 512, (long)1536 * 512);
    zero_h<<<256, 256>>>();

    gemm_mma<<<dim3(12, 256), 256, GEMM_SMEM>>>(Ah, Bh, bie, GI0, 1024, 0);
    gemm_mma<<<dim3(12, 48), 256, GEMM_SMEM>>>(A1h, B1h, bid, GI1, 512, 1);

    rnn_persist<<<128, 256, SMEM_P>>>(Whe, bhe, Whd, Wid, bhd, out);
}